// round 7
// baseline (speedup 1.0000x reference)
#include <cuda_runtime.h>

#define Nn 4096
#define Bb 4
#define Cc 128
#define Hh 8
#define Vv 16
#define HV 128

#define BM 128
#define BN 64
#define BK 32

// Static device scratch (no allocation allowed)
__device__ float g_value[(size_t)Hh * Nn * 64];   // value2[h][j][b*16+v], 8MB
__device__ float g_rowstats[3 * Nn];              // [0..N) d_lo, [N..2N) d_hi, [2N..3N) d_min

__device__ __forceinline__ float read_pct(const int* p) {
    if (!p) return 64.0f;
    int v = *p;
    if (v >= 0 && v <= 100) return (float)v;           // int32 / int64-low-word
    float f = __int_as_float(v);                        // defensive: float32 payload
    if (f >= 0.0f && f <= 100.0f) return f;
    return 64.0f;
}

// ---------------------------------------------------------------------------
// Kernel 1: per-row of dist, compute order statistics k0, k0+1 (radix select
// on float bit patterns, exact & tie-safe for non-negative floats) + row min.
// One block (256 threads) per row.
// ---------------------------------------------------------------------------
__global__ void __launch_bounds__(256, 1) rowstats_kernel(
    const float* __restrict__ dist, const int* __restrict__ locp) {
    __shared__ unsigned keys[Nn];
    __shared__ unsigned hist[256];
    __shared__ unsigned wsums[8];
    __shared__ unsigned sb[2];
    __shared__ float smin[256];

    const int row = blockIdx.x;
    const int t = threadIdx.x;

    const float* rp = dist + (size_t)row * Nn;
    float mn = 3.4e38f;
    for (int i = t; i < Nn; i += 256) {
        float v = rp[i];
        keys[i] = __float_as_uint(v);
        mn = fminf(mn, v);
    }
    smin[t] = mn;
    __syncthreads();
    for (int s = 128; s > 0; s >>= 1) {
        if (t < s) smin[t] = fminf(smin[t], smin[t + s]);
        __syncthreads();
    }

    float pct = read_pct(locp);
    float q = pct / 100.0f;
    float fidx = q * (float)(Nn - 1);
    int k0 = (int)floorf(fidx);
    if (k0 < 0) k0 = 0;
    if (k0 > Nn - 1) k0 = Nn - 1;
    int k1 = (k0 + 1 < Nn) ? (k0 + 1) : (Nn - 1);

    unsigned res[2];
    int targets[2];
    targets[0] = k0;
    targets[1] = k1;

    for (int s = 0; s < 2; s++) {
        int k = targets[s];
        unsigned prefix = 0u, pmask = 0u;
        for (int shift = 24; shift >= 0; shift -= 8) {
            hist[t] = 0u;
            __syncthreads();
            for (int i = t; i < Nn; i += 256) {
                unsigned key = keys[i];
                if ((key & pmask) == prefix)
                    atomicAdd(&hist[(key >> shift) & 255u], 1u);
            }
            __syncthreads();
            unsigned c = hist[t];
            unsigned v = c;
            #pragma unroll
            for (int o = 1; o < 32; o <<= 1) {
                unsigned u = __shfl_up_sync(0xffffffffu, v, o);
                if ((t & 31) >= o) v += u;
            }
            if ((t & 31) == 31) wsums[t >> 5] = v;
            __syncthreads();
            if (t < 8) {
                unsigned w = wsums[t];
                #pragma unroll
                for (int o = 1; o < 8; o <<= 1) {
                    unsigned u = __shfl_up_sync(0xffu, w, o);
                    if (t >= o) w += u;
                }
                wsums[t] = w;
            }
            __syncthreads();
            unsigned incl = v + ((t >= 32) ? wsums[(t >> 5) - 1] : 0u);
            unsigned excl = incl - c;
            if ((unsigned)k >= excl && (unsigned)k < incl) {
                sb[0] = (unsigned)t;
                sb[1] = excl;
            }
            __syncthreads();
            prefix |= sb[0] << shift;
            pmask |= 0xFFu << shift;
            k -= (int)sb[1];
            __syncthreads();
        }
        res[s] = prefix;
    }

    if (t == 0) {
        g_rowstats[row] = __uint_as_float(res[0]);
        g_rowstats[Nn + row] = __uint_as_float(res[1]);
        g_rowstats[2 * Nn + row] = smin[0];
    }
}

// ---------------------------------------------------------------------------
// Kernel 2: value2[h][j][b*16+v] = sum_c inputs[b,j,c] * weight[h,c,v]
// grid (N/64, H), block 512: low 6 bits = c2 (b*16+v), high 3 bits = j lane.
// Outer loop of 2 x inner unroll of 4 keeps regs under the 128 cap.
// ---------------------------------------------------------------------------
__global__ void __launch_bounds__(512, 1) value_kernel(
    const float* __restrict__ inputs, const float* __restrict__ weight) {
    __shared__ float wsm[Cc * Vv];  // 8KB
    const int h = blockIdx.y;
    const int j0 = blockIdx.x * 64;
    const int tid = threadIdx.x;

    for (int e = tid; e < Cc * Vv; e += 512) wsm[e] = weight[h * (Cc * Vv) + e];
    __syncthreads();

    const int c2 = tid & 63;
    const int jj = tid >> 6;  // 0..7
    const int b = c2 >> 4;
    const int v = c2 & 15;

    for (int lo = 0; lo < 2; lo++) {
        #pragma unroll
        for (int li = 0; li < 4; li++) {
            int j = j0 + jj + (lo * 4 + li) * 8;
            const float4* ip = (const float4*)(inputs + ((size_t)b * Nn + j) * Cc);
            float acc = 0.0f;
            #pragma unroll
            for (int c4 = 0; c4 < Cc / 4; c4++) {
                float4 x = ip[c4];
                acc += x.x * wsm[(c4 * 4 + 0) * Vv + v];
                acc += x.y * wsm[(c4 * 4 + 1) * Vv + v];
                acc += x.z * wsm[(c4 * 4 + 2) * Vv + v];
                acc += x.w * wsm[(c4 * 4 + 3) * Vv + v];
            }
            g_value[((size_t)h * Nn + j) * 64 + c2] = acc;
        }
    }
}

// ---------------------------------------------------------------------------
// Kernel 3: fused masked-softmax attention GEMM + normalize + GELU.
// Per block: head h, 128 rows i, all 64 output cols (b*16+v).
// A tile (w weights) generated on the fly from dist; row sums accumulated in
// registers during generation; epilogue divides by sum and applies exact gelu.
// ---------------------------------------------------------------------------
__global__ void __launch_bounds__(256, 2) att_kernel(
    const float* __restrict__ dist, const float* __restrict__ r_in,
    const int* __restrict__ locp, float* __restrict__ out) {
    __shared__ float As[BM][BK];   // w[i][k], stride 32 -> conflict-free
    __shared__ float Bs[BK][BN];   // value2[k][c2]
    __shared__ float maskS[BM];
    __shared__ float shiftS[BM];
    __shared__ float wsumS[BM];
    __shared__ float s_t;

    const int h = blockIdx.y;
    const int i0 = blockIdx.x * BM;
    const int tid = threadIdx.x;

    if (tid == 0) {
        // match reference: z = (pi/4)*(1+sin r) quantized in fp32, then tan
        float sr = sinf(r_in[h]);
        float z = 0.78539816339744831f * (1.0f + sr);
        s_t = (float)tan((double)z);
    }
    __syncthreads();
    const float th = s_t;

    {
        float pct = read_pct(locp);
        float q = pct / 100.0f;
        float fidx = q * (float)(Nn - 1);
        float frac = fidx - floorf(fidx);
        float lw = 1.0f - frac;
        if (tid < BM) {
            int i = i0 + tid;
            float v0 = th * g_rowstats[i];
            float v1 = th * g_rowstats[Nn + i];
            maskS[tid] = v0 * lw + v1 * frac;        // jnp linear interpolation
            shiftS[tid] = th * g_rowstats[2 * Nn + i];  // t * row-min (softmax max)
        }
    }
    __syncthreads();

    const int kk = tid & 31;   // j within tile (coalesced dist read)
    const int ib = tid >> 5;   // 0..7 (== warp id)
    const int tx = tid & 15;
    const int ty = tid >> 4;
    const int c2 = tid & 63;
    const int kr = tid >> 6;

    const float* dbase = dist + (size_t)(i0 + ib) * Nn + kk;
    const float* vbase = g_value + (size_t)h * Nn * 64;

    float acc[8][4];
    #pragma unroll
    for (int m = 0; m < 8; m++)
        #pragma unroll
        for (int n = 0; n < 4; n++) acc[m][n] = 0.0f;
    float rowacc[16];
    #pragma unroll
    for (int l = 0; l < 16; l++) rowacc[l] = 0.0f;

    for (int j0 = 0; j0 < Nn; j0 += BK) {
        // generate w tile (A) from dist
        #pragma unroll
        for (int l = 0; l < 16; l++) {
            int il = ib + l * 8;
            float d = dbase[(size_t)l * 8 * Nn + j0];
            float sd = th * d;
            float w = (sd <= maskS[il]) ? __expf(shiftS[il] - sd) : 0.0f;
            As[il][kk] = w;
            rowacc[l] += w;
        }
        // load B tile (value2)
        {
            const float* src = vbase + (size_t)j0 * 64;
            #pragma unroll
            for (int l = 0; l < 8; l++) {
                int k = kr + l * 4;
                Bs[k][c2] = src[k * 64 + c2];
            }
        }
        __syncthreads();
        #pragma unroll
        for (int k = 0; k < BK; k++) {
            float4 bv = *(const float4*)(&Bs[k][tx * 4]);
            float a[8];
            #pragma unroll
            for (int m = 0; m < 8; m++) a[m] = As[ty * 8 + m][k];
            #pragma unroll
            for (int m = 0; m < 8; m++) {
                acc[m][0] += a[m] * bv.x;
                acc[m][1] += a[m] * bv.y;
                acc[m][2] += a[m] * bv.z;
                acc[m][3] += a[m] * bv.w;
            }
        }
        __syncthreads();
    }

    // row sums: all 32 lanes of a warp share the same row set -> warp reduce
    #pragma unroll
    for (int l = 0; l < 16; l++) {
        float s = rowacc[l];
        #pragma unroll
        for (int o = 16; o > 0; o >>= 1) s += __shfl_down_sync(0xffffffffu, s, o);
        if ((tid & 31) == 0) wsumS[ib + l * 8] = s;
    }
    __syncthreads();

    // epilogue: normalize, exact gelu, write out[b][i][h*16+v]
    const int b = tx >> 2;
    const int vv0 = (tx & 3) * 4;
    #pragma unroll
    for (int m = 0; m < 8; m++) {
        int i = i0 + ty * 8 + m;
        float inv = 1.0f / wsumS[ty * 8 + m];
        float4 o;
        float x;
        x = acc[m][0] * inv; o.x = 0.5f * x * (1.0f + erff(x * 0.70710678118654752f));
        x = acc[m][1] * inv; o.y = 0.5f * x * (1.0f + erff(x * 0.70710678118654752f));
        x = acc[m][2] * inv; o.z = 0.5f * x * (1.0f + erff(x * 0.70710678118654752f));
        x = acc[m][3] * inv; o.w = 0.5f * x * (1.0f + erff(x * 0.70710678118654752f));
        *(float4*)(&out[((size_t)b * Nn + i) * HV + h * Vv + vv0]) = o;
    }
}

extern "C" void kernel_launch(void* const* d_in, const int* in_sizes, int n_in,
                              void* d_out, int out_size) {
    const float* inputs = (const float*)d_in[0];
    const float* dist   = (const float*)d_in[1];
    const float* r      = (const float*)d_in[2];
    const float* weight = (const float*)d_in[3];
    const int*   locp   = (n_in > 4) ? (const int*)d_in[4] : nullptr;
    float* out = (float*)d_out;
    (void)in_sizes; (void)out_size;

    rowstats_kernel<<<Nn, 256>>>(dist, locp);
    value_kernel<<<dim3(Nn / 64, Hh), 512>>>(inputs, weight);
    att_kernel<<<dim3(Nn / BM, Hh), 256>>>(dist, r, locp, out);
}

// round 8
// speedup vs baseline: 1.1103x; 1.1103x over previous
#include <cuda_runtime.h>

#define Nn 4096
#define Bb 4
#define Cc 128
#define Hh 8
#define Vv 16
#define HV 128

#define BM 128
#define BN 64
#define BK 32
#define APAD 2   // Ast row pad (floats): keeps STS conflicts at 2-way, LDS.64 aligned

// Static device scratch (no allocation allowed)
__device__ float g_value[(size_t)Hh * Nn * 64];   // value2[h][j][b*16+v], 8MB
__device__ float g_rowstats[3 * Nn];              // [0..N) d_lo, [N..2N) d_hi, [2N..3N) d_min

__device__ __forceinline__ float read_pct(const int* p) {
    if (!p) return 64.0f;
    int v = *p;
    if (v >= 0 && v <= 100) return (float)v;
    float f = __int_as_float(v);
    if (f >= 0.0f && f <= 100.0f) return f;
    return 64.0f;
}

// packed f32x2 helpers (FFMA2 path — only reachable via PTX)
#define PACK2(out, lo, hi) \
    asm("mov.b64 %0, {%1, %2};" : "=l"(out) : "r"(__float_as_uint(lo)), "r"(__float_as_uint(hi)))
#define UNPACK2(lo, hi, in) \
    asm("mov.b64 {%0, %1}, %2;" : "=f"(lo), "=f"(hi) : "l"(in))
#define FMA2(acc, a, b) \
    asm("fma.rn.f32x2 %0, %1, %2, %0;" : "+l"(acc) : "l"(a), "l"(b))

// ---------------------------------------------------------------------------
// Kernel 1: per row of dist: k0-th order statistic via radix select (exact,
// tie-safe on non-negative float bit patterns), k0+1-th derived from one
// extra pass (count<=val0 and min-above-val0), plus row min.
// ---------------------------------------------------------------------------
__global__ void __launch_bounds__(256, 1) rowstats_kernel(
    const float* __restrict__ dist, const int* __restrict__ locp) {
    __shared__ unsigned keys[Nn];
    __shared__ unsigned hist[256];
    __shared__ unsigned wsums[8];
    __shared__ unsigned sb[2];
    __shared__ float smin[256];
    __shared__ unsigned s_cntLE;
    __shared__ unsigned s_minAbove;

    const int row = blockIdx.x;
    const int t = threadIdx.x;

    const float* rp = dist + (size_t)row * Nn;
    float mn = 3.4e38f;
    for (int i = t; i < Nn; i += 256) {
        float v = rp[i];
        keys[i] = __float_as_uint(v);
        mn = fminf(mn, v);
    }
    smin[t] = mn;
    if (t == 0) { s_cntLE = 0u; s_minAbove = 0xFFFFFFFFu; }
    __syncthreads();
    for (int s = 128; s > 0; s >>= 1) {
        if (t < s) smin[t] = fminf(smin[t], smin[t + s]);
        __syncthreads();
    }

    float pct = read_pct(locp);
    float q = pct / 100.0f;
    float fidx = q * (float)(Nn - 1);
    int k0 = (int)floorf(fidx);
    if (k0 < 0) k0 = 0;
    if (k0 > Nn - 1) k0 = Nn - 1;

    // single radix descent for rank k0
    int k = k0;
    unsigned prefix = 0u, pmask = 0u;
    for (int shift = 24; shift >= 0; shift -= 8) {
        hist[t] = 0u;
        __syncthreads();
        for (int i = t; i < Nn; i += 256) {
            unsigned key = keys[i];
            if ((key & pmask) == prefix)
                atomicAdd(&hist[(key >> shift) & 255u], 1u);
        }
        __syncthreads();
        unsigned c = hist[t];
        unsigned v = c;
        #pragma unroll
        for (int o = 1; o < 32; o <<= 1) {
            unsigned u = __shfl_up_sync(0xffffffffu, v, o);
            if ((t & 31) >= o) v += u;
        }
        if ((t & 31) == 31) wsums[t >> 5] = v;
        __syncthreads();
        if (t < 8) {
            unsigned w = wsums[t];
            #pragma unroll
            for (int o = 1; o < 8; o <<= 1) {
                unsigned u = __shfl_up_sync(0xffu, w, o);
                if (t >= o) w += u;
            }
            wsums[t] = w;
        }
        __syncthreads();
        unsigned incl = v + ((t >= 32) ? wsums[(t >> 5) - 1] : 0u);
        unsigned excl = incl - c;
        if ((unsigned)k >= excl && (unsigned)k < incl) {
            sb[0] = (unsigned)t;
            sb[1] = excl;
        }
        __syncthreads();
        prefix |= sb[0] << shift;
        pmask |= 0xFFu << shift;
        k -= (int)sb[1];
        __syncthreads();
    }
    const unsigned val0 = prefix;

    // one pass: count(keys <= val0) and min(keys > val0)
    {
        unsigned lcnt = 0u, lmin = 0xFFFFFFFFu;
        for (int i = t; i < Nn; i += 256) {
            unsigned key = keys[i];
            if (key <= val0) lcnt++;
            else lmin = min(lmin, key);
        }
        #pragma unroll
        for (int o = 16; o > 0; o >>= 1) {
            lcnt += __shfl_down_sync(0xffffffffu, lcnt, o);
            lmin = min(lmin, __shfl_down_sync(0xffffffffu, lmin, o));
        }
        if ((t & 31) == 0) {
            atomicAdd(&s_cntLE, lcnt);
            atomicMin(&s_minAbove, lmin);
        }
    }
    __syncthreads();

    if (t == 0) {
        unsigned val1;
        int k1 = (k0 + 1 < Nn) ? (k0 + 1) : (Nn - 1);
        if (k1 == k0 || (unsigned)k1 < s_cntLE) val1 = val0;
        else val1 = s_minAbove;
        g_rowstats[row] = __uint_as_float(val0);
        g_rowstats[Nn + row] = __uint_as_float(val1);
        g_rowstats[2 * Nn + row] = smin[0];
    }
}

// ---------------------------------------------------------------------------
// Kernel 2: value2[h][j][b*16+v] = sum_c inputs[b,j,c] * weight[h,c,v]
// ---------------------------------------------------------------------------
__global__ void __launch_bounds__(512, 1) value_kernel(
    const float* __restrict__ inputs, const float* __restrict__ weight) {
    __shared__ float wsm[Cc * Vv];  // 8KB
    const int h = blockIdx.y;
    const int j0 = blockIdx.x * 64;
    const int tid = threadIdx.x;

    for (int e = tid; e < Cc * Vv; e += 512) wsm[e] = weight[h * (Cc * Vv) + e];
    __syncthreads();

    const int c2 = tid & 63;
    const int jj = tid >> 6;  // 0..7
    const int b = c2 >> 4;
    const int v = c2 & 15;

    for (int lo = 0; lo < 2; lo++) {
        #pragma unroll
        for (int li = 0; li < 4; li++) {
            int j = j0 + jj + (lo * 4 + li) * 8;
            const float4* ip = (const float4*)(inputs + ((size_t)b * Nn + j) * Cc);
            float acc = 0.0f;
            #pragma unroll
            for (int c4 = 0; c4 < Cc / 4; c4++) {
                float4 x = ip[c4];
                acc += x.x * wsm[(c4 * 4 + 0) * Vv + v];
                acc += x.y * wsm[(c4 * 4 + 1) * Vv + v];
                acc += x.z * wsm[(c4 * 4 + 2) * Vv + v];
                acc += x.w * wsm[(c4 * 4 + 3) * Vv + v];
            }
            g_value[((size_t)h * Nn + j) * 64 + c2] = acc;
        }
    }
}

// ---------------------------------------------------------------------------
// Kernel 3: fused masked-softmax attention GEMM + normalize + GELU.
// f32x2 (FFMA2) mainloop: rows paired along M. A tile stored transposed
// Ast[k][i] so row pairs load as one LDS.64; B scalars broadcast-packed.
// ---------------------------------------------------------------------------
__global__ void __launch_bounds__(256, 2) att_kernel(
    const float* __restrict__ dist, const float* __restrict__ r_in,
    const int* __restrict__ locp, float* __restrict__ out) {
    __shared__ float Ast[BK][BM + APAD];  // w[k][i] (transposed)
    __shared__ float Bs[BK][BN];          // value2[k][c2]
    __shared__ float maskS[BM];
    __shared__ float shiftS[BM];
    __shared__ float wsumS[BM];
    __shared__ float s_t;

    const int h = blockIdx.y;
    const int i0 = blockIdx.x * BM;
    const int tid = threadIdx.x;

    if (tid == 0) {
        // match reference: z = (pi/4)*(1+sin r) quantized in fp32, then tan
        float sr = sinf(r_in[h]);
        float z = 0.78539816339744831f * (1.0f + sr);
        s_t = (float)tan((double)z);
    }
    __syncthreads();
    const float th = s_t;

    {
        float pct = read_pct(locp);
        float q = pct / 100.0f;
        float fidx = q * (float)(Nn - 1);
        float frac = fidx - floorf(fidx);
        float lw = 1.0f - frac;
        if (tid < BM) {
            int i = i0 + tid;
            float v0 = th * g_rowstats[i];
            float v1 = th * g_rowstats[Nn + i];
            maskS[tid] = v0 * lw + v1 * frac;           // jnp linear interpolation
            shiftS[tid] = th * g_rowstats[2 * Nn + i];  // t * row-min (softmax shift)
        }
    }
    __syncthreads();

    const int kk = tid & 31;   // j within tile (coalesced dist read)
    const int ib = tid >> 5;   // warp id = row sub-index for generation
    const int tx = tid & 15;   // output column group (4 cols)
    const int ty = tid >> 4;   // row group (8 rows = 4 pairs)
    const int c2 = tid & 63;
    const int kr = tid >> 6;

    const float* dbase = dist + (size_t)(i0 + ib) * Nn + kk;
    const float* vbase = g_value + (size_t)h * Nn * 64;

    unsigned long long acc2[4][4];  // [row-pair][col] : packed {row 2mp, row 2mp+1}
    #pragma unroll
    for (int mp = 0; mp < 4; mp++)
        #pragma unroll
        for (int n = 0; n < 4; n++) acc2[mp][n] = 0ull;
    float rowacc[16];
    #pragma unroll
    for (int l = 0; l < 16; l++) rowacc[l] = 0.0f;

    for (int j0 = 0; j0 < Nn; j0 += BK) {
        // generate w tile (A, transposed) from dist
        #pragma unroll
        for (int l = 0; l < 16; l++) {
            int il = ib + l * 8;
            float d = dbase[(size_t)l * 8 * Nn + j0];
            float sd = th * d;
            float w = (sd <= maskS[il]) ? __expf(shiftS[il] - sd) : 0.0f;
            Ast[kk][il] = w;
            rowacc[l] += w;
        }
        // load B tile (value2)
        {
            const float* src = vbase + (size_t)j0 * 64;
            #pragma unroll
            for (int l = 0; l < 8; l++) {
                int kq = kr + l * 4;
                Bs[kq][c2] = src[kq * 64 + c2];
            }
        }
        __syncthreads();
        #pragma unroll
        for (int kc = 0; kc < BK; kc++) {
            float4 bv = *(const float4*)(&Bs[kc][tx * 4]);
            unsigned long long bb[4];
            PACK2(bb[0], bv.x, bv.x);
            PACK2(bb[1], bv.y, bv.y);
            PACK2(bb[2], bv.z, bv.z);
            PACK2(bb[3], bv.w, bv.w);
            const unsigned long long* ap =
                (const unsigned long long*)&Ast[kc][ty * 8];
            unsigned long long a2[4];
            #pragma unroll
            for (int mp = 0; mp < 4; mp++) a2[mp] = ap[mp];
            #pragma unroll
            for (int mp = 0; mp < 4; mp++) {
                FMA2(acc2[mp][0], a2[mp], bb[0]);
                FMA2(acc2[mp][1], a2[mp], bb[1]);
                FMA2(acc2[mp][2], a2[mp], bb[2]);
                FMA2(acc2[mp][3], a2[mp], bb[3]);
            }
        }
        __syncthreads();
    }

    // row sums: all 32 lanes of a warp share the same row set -> warp reduce
    #pragma unroll
    for (int l = 0; l < 16; l++) {
        float s = rowacc[l];
        #pragma unroll
        for (int o = 16; o > 0; o >>= 1) s += __shfl_down_sync(0xffffffffu, s, o);
        if ((tid & 31) == 0) wsumS[ib + l * 8] = s;
    }
    __syncthreads();

    // epilogue: unpack, normalize, exact gelu, write out[b][i][h*16+v]
    const int b = tx >> 2;
    const int vv0 = (tx & 3) * 4;
    #pragma unroll
    for (int mp = 0; mp < 4; mp++) {
        float lo[4], hi[4];
        #pragma unroll
        for (int n = 0; n < 4; n++) UNPACK2(lo[n], hi[n], acc2[mp][n]);
        int rloc0 = ty * 8 + 2 * mp;
        float inv0 = 1.0f / wsumS[rloc0];
        float inv1 = 1.0f / wsumS[rloc0 + 1];
        float4 o0, o1;
        float x;
        x = lo[0] * inv0; o0.x = 0.5f * x * (1.0f + erff(x * 0.70710678118654752f));
        x = lo[1] * inv0; o0.y = 0.5f * x * (1.0f + erff(x * 0.70710678118654752f));
        x = lo[2] * inv0; o0.z = 0.5f * x * (1.0f + erff(x * 0.70710678118654752f));
        x = lo[3] * inv0; o0.w = 0.5f * x * (1.0f + erff(x * 0.70710678118654752f));
        x = hi[0] * inv1; o1.x = 0.5f * x * (1.0f + erff(x * 0.70710678118654752f));
        x = hi[1] * inv1; o1.y = 0.5f * x * (1.0f + erff(x * 0.70710678118654752f));
        x = hi[2] * inv1; o1.z = 0.5f * x * (1.0f + erff(x * 0.70710678118654752f));
        x = hi[3] * inv1; o1.w = 0.5f * x * (1.0f + erff(x * 0.70710678118654752f));
        int i0g = i0 + rloc0;
        *(float4*)(&out[((size_t)b * Nn + i0g) * HV + h * Vv + vv0]) = o0;
        *(float4*)(&out[((size_t)b * Nn + i0g + 1) * HV + h * Vv + vv0]) = o1;
    }
}

extern "C" void kernel_launch(void* const* d_in, const int* in_sizes, int n_in,
                              void* d_out, int out_size) {
    const float* inputs = (const float*)d_in[0];
    const float* dist   = (const float*)d_in[1];
    const float* r      = (const float*)d_in[2];
    const float* weight = (const float*)d_in[3];
    const int*   locp   = (n_in > 4) ? (const int*)d_in[4] : nullptr;
    float* out = (float*)d_out;
    (void)in_sizes; (void)out_size;

    rowstats_kernel<<<Nn, 256>>>(dist, locp);
    value_kernel<<<dim3(Nn / 64, Hh), 512>>>(inputs, weight);
    att_kernel<<<dim3(Nn / BM, Hh), 256>>>(dist, r, locp, out);
}

// round 10
// speedup vs baseline: 1.8287x; 1.6470x over previous
#include <cuda_runtime.h>
#include <cuda_bf16.h>
#include <cstdint>

#define Nn 4096
#define Bb 4
#define Cc 128
#define Hh 8
#define Vv 16
#define HV 128

// ---------------- static device scratch ------------------------------------
__device__ __align__(16) __nv_bfloat16 g_vh[(size_t)Hh * 64 * Nn];  // value hi plane [h][c2][j]
__device__ __align__(16) __nv_bfloat16 g_vl[(size_t)Hh * 64 * Nn];  // value lo plane
__device__ float g_rowstats[3 * Nn];  // [0..N) d_lo, [N..2N) d_hi, [2N..3N) d_min

__device__ __forceinline__ float read_pct(const int* p) {
    if (!p) return 64.0f;
    int v = *p;
    if (v >= 0 && v <= 100) return (float)v;
    float f = __int_as_float(v);
    if (f >= 0.0f && f <= 100.0f) return f;
    return 64.0f;
}

// warp-level bf16 tensor-core mma (sm_80+ PTX, valid on base sm_103 target)
#define MMA_BF16(c0, c1, c2, c3, a0, a1, a2, a3, b0, b1)                      \
    asm volatile(                                                             \
        "mma.sync.aligned.m16n8k16.row.col.f32.bf16.bf16.f32 "                \
        "{%0,%1,%2,%3}, {%4,%5,%6,%7}, {%8,%9}, {%0,%1,%2,%3};"               \
        : "+f"(c0), "+f"(c1), "+f"(c2), "+f"(c3)                              \
        : "r"(a0), "r"(a1), "r"(a2), "r"(a3), "r"(b0), "r"(b1))

// ---------------------------------------------------------------------------
// Kernel 1: per row of dist: rank-k0 order statistic (radix select, exact,
// tie-safe on non-negative float bit patterns), rank-k0+1 from one extra
// pass, plus row min.
// ---------------------------------------------------------------------------
__global__ void __launch_bounds__(256, 1) rowstats_kernel(
    const float* __restrict__ dist, const int* __restrict__ locp) {
    __shared__ unsigned keys[Nn];
    __shared__ unsigned hist[256];
    __shared__ unsigned wsums[8];
    __shared__ unsigned sb[2];
    __shared__ float smin[256];
    __shared__ unsigned s_cntLE;
    __shared__ unsigned s_minAbove;

    const int row = blockIdx.x;
    const int t = threadIdx.x;

    const float* rp = dist + (size_t)row * Nn;
    float mn = 3.4e38f;
    for (int i = t; i < Nn; i += 256) {
        float v = rp[i];
        keys[i] = __float_as_uint(v);
        mn = fminf(mn, v);
    }
    smin[t] = mn;
    if (t == 0) { s_cntLE = 0u; s_minAbove = 0xFFFFFFFFu; }
    __syncthreads();
    for (int s = 128; s > 0; s >>= 1) {
        if (t < s) smin[t] = fminf(smin[t], smin[t + s]);
        __syncthreads();
    }

    float pct = read_pct(locp);
    float q = pct / 100.0f;
    float fidx = q * (float)(Nn - 1);
    int k0 = (int)floorf(fidx);
    if (k0 < 0) k0 = 0;
    if (k0 > Nn - 1) k0 = Nn - 1;

    int k = k0;
    unsigned prefix = 0u, pmask = 0u;
    for (int shift = 24; shift >= 0; shift -= 8) {
        hist[t] = 0u;
        __syncthreads();
        for (int i = t; i < Nn; i += 256) {
            unsigned key = keys[i];
            if ((key & pmask) == prefix)
                atomicAdd(&hist[(key >> shift) & 255u], 1u);
        }
        __syncthreads();
        unsigned c = hist[t];
        unsigned v = c;
        #pragma unroll
        for (int o = 1; o < 32; o <<= 1) {
            unsigned u = __shfl_up_sync(0xffffffffu, v, o);
            if ((t & 31) >= o) v += u;
        }
        if ((t & 31) == 31) wsums[t >> 5] = v;
        __syncthreads();
        if (t < 8) {
            unsigned w = wsums[t];
            #pragma unroll
            for (int o = 1; o < 8; o <<= 1) {
                unsigned u = __shfl_up_sync(0xffu, w, o);
                if (t >= o) w += u;
            }
            wsums[t] = w;
        }
        __syncthreads();
        unsigned incl = v + ((t >= 32) ? wsums[(t >> 5) - 1] : 0u);
        unsigned excl = incl - c;
        if ((unsigned)k >= excl && (unsigned)k < incl) {
            sb[0] = (unsigned)t;
            sb[1] = excl;
        }
        __syncthreads();
        prefix |= sb[0] << shift;
        pmask |= 0xFFu << shift;
        k -= (int)sb[1];
        __syncthreads();
    }
    const unsigned val0 = prefix;

    {
        unsigned lcnt = 0u, lmin = 0xFFFFFFFFu;
        for (int i = t; i < Nn; i += 256) {
            unsigned key = keys[i];
            if (key <= val0) lcnt++;
            else lmin = min(lmin, key);
        }
        #pragma unroll
        for (int o = 16; o > 0; o >>= 1) {
            lcnt += __shfl_down_sync(0xffffffffu, lcnt, o);
            lmin = min(lmin, __shfl_down_sync(0xffffffffu, lmin, o));
        }
        if ((t & 31) == 0) {
            atomicAdd(&s_cntLE, lcnt);
            atomicMin(&s_minAbove, lmin);
        }
    }
    __syncthreads();

    if (t == 0) {
        unsigned val1;
        int k1 = (k0 + 1 < Nn) ? (k0 + 1) : (Nn - 1);
        if (k1 == k0 || (unsigned)k1 < s_cntLE) val1 = val0;
        else val1 = s_minAbove;
        g_rowstats[row] = __uint_as_float(val0);
        g_rowstats[Nn + row] = __uint_as_float(val1);
        g_rowstats[2 * Nn + row] = smin[0];
    }
}

// ---------------------------------------------------------------------------
// Kernel 2: value[h][j][c2] = sum_c inputs[b,j,c]*weight[h,c,v]  (c2=b*16+v),
// split into bf16 hi/lo and written TRANSPOSED: g_vh/g_vl[h][c2][j].
// ---------------------------------------------------------------------------
__global__ void __launch_bounds__(512, 1) value_kernel(
    const float* __restrict__ inputs, const float* __restrict__ weight) {
    __shared__ float wsm[Cc * Vv];                 // 8KB
    __shared__ __nv_bfloat16 shT[64][72];          // [c2][j] hi
    __shared__ __nv_bfloat16 slT[64][72];          // [c2][j] lo
    const int h = blockIdx.y;
    const int j0 = blockIdx.x * 64;
    const int tid = threadIdx.x;

    for (int e = tid; e < Cc * Vv; e += 512) wsm[e] = weight[h * (Cc * Vv) + e];
    __syncthreads();

    const int c2 = tid & 63;
    const int jj = tid >> 6;  // 0..7
    const int b = c2 >> 4;
    const int v = c2 & 15;

    #pragma unroll
    for (int l = 0; l < 8; l++) {
        int jl = jj + l * 8;
        int j = j0 + jl;
        const float4* ip = (const float4*)(inputs + ((size_t)b * Nn + j) * Cc);
        float acc = 0.0f;
        #pragma unroll
        for (int c4 = 0; c4 < Cc / 4; c4++) {
            float4 x = ip[c4];
            acc += x.x * wsm[(c4 * 4 + 0) * Vv + v];
            acc += x.y * wsm[(c4 * 4 + 1) * Vv + v];
            acc += x.z * wsm[(c4 * 4 + 2) * Vv + v];
            acc += x.w * wsm[(c4 * 4 + 3) * Vv + v];
        }
        __nv_bfloat16 hi = __float2bfloat16(acc);
        __nv_bfloat16 lo = __float2bfloat16(acc - __bfloat162float(hi));
        shT[c2][jl] = hi;
        slT[c2][jl] = lo;
    }
    __syncthreads();

    const int c2r = tid >> 3;  // 0..63
    const int seg = tid & 7;   // 0..7
    uint4 vh = *(const uint4*)&shT[c2r][seg * 8];
    uint4 vl = *(const uint4*)&slT[c2r][seg * 8];
    size_t off = ((size_t)h * 64 + c2r) * Nn + j0 + seg * 8;
    *(uint4*)(g_vh + off) = vh;
    *(uint4*)(g_vl + off) = vl;
}

// ---------------------------------------------------------------------------
// Kernel 3: fused masked-softmax attention via mma.sync bf16 (split-2, 3
// products: hh + hl + lh; lo*lo dropped, ~2^-18 rel).
// Block: 128 rows x head. Warp w owns rows 16w..16w+15, all 64 cols.
// Per K=64 tile: generate W hi/lo (bf16, row-major, pitch 72), copy V hi/lo
// ([n][k], pitch 72), then fragments via direct conflict-free LDS.32.
// Row softmax sums accumulated in registers during generation.
// ---------------------------------------------------------------------------
#define PITCHB 144            // 72 bf16 per row
#define S_WH 0                // 128 rows * 144B = 18432
#define S_WL 18432
#define S_VH 36864            // 64 rows * 144B = 9216
#define S_VL 46080
#define S_WS 55296            // float wsum[128]
#define S_TOTAL 55936

__global__ void __launch_bounds__(256, 2) att_kernel(
    const float* __restrict__ dist, const float* __restrict__ r_in,
    const int* __restrict__ locp, float* __restrict__ out) {
    extern __shared__ char smem[];
    const int tid = threadIdx.x;
    const int wid = tid >> 5;
    const int lid = tid & 31;
    const int h = blockIdx.y;
    const int i0 = blockIdx.x * 128;

    // th = tan((pi/4)*(1+sin r)) with fp32-quantized argument (matches ref)
    float th;
    {
        float sr = sinf(r_in[h]);
        float z = 0.78539816339744831f * (1.0f + sr);
        th = (float)tan((double)z);
    }

    // generation mapping: thread (rg, kk2) covers rows rg+16l, j pairs kk2
    const int kk2 = tid & 15;
    const int rg = tid >> 4;
    float maskR[8], shiftR[8], rowacc[8];
    {
        float pct = read_pct(locp);
        float q = pct / 100.0f;
        float fidx = q * (float)(Nn - 1);
        float frac = fidx - floorf(fidx);
        float lw = 1.0f - frac;
        #pragma unroll
        for (int l = 0; l < 8; l++) {
            int i = i0 + rg + 16 * l;
            float v0 = th * g_rowstats[i];
            float v1 = th * g_rowstats[Nn + i];
            maskR[l] = v0 * lw + v1 * frac;           // jnp linear interpolation
            shiftR[l] = th * g_rowstats[2 * Nn + i];  // th * row-min (softmax shift)
            rowacc[l] = 0.0f;
        }
    }

    const __nv_bfloat16* vhp = g_vh + (size_t)h * 64 * Nn;
    const __nv_bfloat16* vlp = g_vl + (size_t)h * 64 * Nn;

    // mma lane mapping
    const int g = lid >> 2;   // 0..7
    const int tq = lid & 3;   // 0..3

    float acc[8][4];
    #pragma unroll
    for (int nt = 0; nt < 8; nt++)
        #pragma unroll
        for (int c = 0; c < 4; c++) acc[nt][c] = 0.0f;

    for (int t = 0; t < Nn / 64; t++) {
        const int j0 = t * 64;
        // ---- generate W tile (hi/lo bf16), accumulate row sums ----
        #pragma unroll
        for (int l = 0; l < 8; l++) {
            int row = rg + 16 * l;
            const float* dr = dist + (size_t)(i0 + row) * Nn + j0 + kk2 * 2;
            float2 dA = *(const float2*)(dr);
            float2 dB = *(const float2*)(dr + 32);
            float m = maskR[l], s = shiftR[l];
            float sd;
            sd = th * dA.x; float w00 = (sd <= m) ? __expf(s - sd) : 0.0f;
            sd = th * dA.y; float w01 = (sd <= m) ? __expf(s - sd) : 0.0f;
            sd = th * dB.x; float w10 = (sd <= m) ? __expf(s - sd) : 0.0f;
            sd = th * dB.y; float w11 = (sd <= m) ? __expf(s - sd) : 0.0f;
            rowacc[l] += (w00 + w01) + (w10 + w11);
            __nv_bfloat16 h00 = __float2bfloat16(w00);
            __nv_bfloat16 h01 = __float2bfloat16(w01);
            __nv_bfloat16 h10 = __float2bfloat16(w10);
            __nv_bfloat16 h11 = __float2bfloat16(w11);
            __nv_bfloat16 l00 = __float2bfloat16(w00 - __bfloat162float(h00));
            __nv_bfloat16 l01 = __float2bfloat16(w01 - __bfloat162float(h01));
            __nv_bfloat16 l10 = __float2bfloat16(w10 - __bfloat162float(h10));
            __nv_bfloat16 l11 = __float2bfloat16(w11 - __bfloat162float(h11));
            uint32_t ph0, pl0, ph1, pl1;
            asm("mov.b32 %0, {%1, %2};" : "=r"(ph0) : "h"(*(const uint16_t*)&h00), "h"(*(const uint16_t*)&h01));
            asm("mov.b32 %0, {%1, %2};" : "=r"(pl0) : "h"(*(const uint16_t*)&l00), "h"(*(const uint16_t*)&l01));
            asm("mov.b32 %0, {%1, %2};" : "=r"(ph1) : "h"(*(const uint16_t*)&h10), "h"(*(const uint16_t*)&h11));
            asm("mov.b32 %0, {%1, %2};" : "=r"(pl1) : "h"(*(const uint16_t*)&l10), "h"(*(const uint16_t*)&l11));
            uint32_t off0 = (uint32_t)row * PITCHB + kk2 * 4;  // k = kk2*2
            uint32_t off1 = off0 + 64;                          // k += 32
            *(uint32_t*)(smem + S_WH + off0) = ph0;
            *(uint32_t*)(smem + S_WL + off0) = pl0;
            *(uint32_t*)(smem + S_WH + off1) = ph1;
            *(uint32_t*)(smem + S_WL + off1) = pl1;
        }
        // ---- copy V tile (hi/lo), V[n][k] with 144B pitch ----
        #pragma unroll
        for (int qq = 0; qq < 2; qq++) {
            int idx = tid + qq * 256;
            int n = idx >> 3;
            int k8 = idx & 7;
            size_t srcoff = ((size_t)n * Nn + j0 + k8 * 8);
            uint32_t off = (uint32_t)n * PITCHB + k8 * 16;
            *(uint4*)(smem + S_VH + off) = *(const uint4*)(vhp + srcoff);
            *(uint4*)(smem + S_VL + off) = *(const uint4*)(vlp + srcoff);
        }
        __syncthreads();
        // ---- mma: warp wid rows 16*wid.., 8 n-tiles, 4 k-steps, 3 products ----
        #pragma unroll
        for (int ks = 0; ks < 4; ks++) {
            const int k0 = ks * 16;
            const uint32_t aoff = (uint32_t)(16 * wid + g) * PITCHB + (k0 + 2 * tq) * 2;
            uint32_t ah0 = *(const uint32_t*)(smem + S_WH + aoff);
            uint32_t ah1 = *(const uint32_t*)(smem + S_WH + aoff + 8 * PITCHB);
            uint32_t ah2 = *(const uint32_t*)(smem + S_WH + aoff + 16);
            uint32_t ah3 = *(const uint32_t*)(smem + S_WH + aoff + 8 * PITCHB + 16);
            uint32_t al0 = *(const uint32_t*)(smem + S_WL + aoff);
            uint32_t al1 = *(const uint32_t*)(smem + S_WL + aoff + 8 * PITCHB);
            uint32_t al2 = *(const uint32_t*)(smem + S_WL + aoff + 16);
            uint32_t al3 = *(const uint32_t*)(smem + S_WL + aoff + 8 * PITCHB + 16);
            #pragma unroll
            for (int nt = 0; nt < 8; nt++) {
                const uint32_t boff = (uint32_t)(8 * nt + g) * PITCHB + (k0 + 2 * tq) * 2;
                uint32_t bh0 = *(const uint32_t*)(smem + S_VH + boff);
                uint32_t bh1 = *(const uint32_t*)(smem + S_VH + boff + 16);
                uint32_t bl0 = *(const uint32_t*)(smem + S_VL + boff);
                uint32_t bl1 = *(const uint32_t*)(smem + S_VL + boff + 16);
                MMA_BF16(acc[nt][0], acc[nt][1], acc[nt][2], acc[nt][3],
                         ah0, ah1, ah2, ah3, bh0, bh1);
                MMA_BF16(acc[nt][0], acc[nt][1], acc[nt][2], acc[nt][3],
                         ah0, ah1, ah2, ah3, bl0, bl1);
                MMA_BF16(acc[nt][0], acc[nt][1], acc[nt][2], acc[nt][3],
                         al0, al1, al2, al3, bh0, bh1);
            }
        }
        __syncthreads();
    }

    // ---- row softmax sums -> shared ----
    float* wsum = (float*)(smem + S_WS);
    #pragma unroll
    for (int l = 0; l < 8; l++) {
        float s = rowacc[l];
        #pragma unroll
        for (int o = 8; o > 0; o >>= 1) s += __shfl_xor_sync(0xffffffffu, s, o);
        if (kk2 == 0) wsum[rg + 16 * l] = s;
    }
    __syncthreads();

    // ---- epilogue: normalize, exact gelu, write ----
    const int row0 = 16 * wid + g;
    const float inv0 = 1.0f / wsum[row0];
    const float inv1 = 1.0f / wsum[row0 + 8];
    #pragma unroll
    for (int nt = 0; nt < 8; nt++) {
        const int col = nt * 8 + 2 * tq;
        const int b = col >> 4;
        const int v = col & 15;
        float x;
        float2 o0, o1;
        x = acc[nt][0] * inv0; o0.x = 0.5f * x * (1.0f + erff(x * 0.70710678118654752f));
        x = acc[nt][1] * inv0; o0.y = 0.5f * x * (1.0f + erff(x * 0.70710678118654752f));
        x = acc[nt][2] * inv1; o1.x = 0.5f * x * (1.0f + erff(x * 0.70710678118654752f));
        x = acc[nt][3] * inv1; o1.y = 0.5f * x * (1.0f + erff(x * 0.70710678118654752f));
        *(float2*)(&out[((size_t)b * Nn + i0 + row0) * HV + h * Vv + v]) = o0;
        *(float2*)(&out[((size_t)b * Nn + i0 + row0 + 8) * HV + h * Vv + v]) = o1;
    }
}

extern "C" void kernel_launch(void* const* d_in, const int* in_sizes, int n_in,
                              void* d_out, int out_size) {
    const float* inputs = (const float*)d_in[0];
    const float* dist   = (const float*)d_in[1];
    const float* r      = (const float*)d_in[2];
    const float* weight = (const float*)d_in[3];
    const int*   locp   = (n_in > 4) ? (const int*)d_in[4] : nullptr;
    float* out = (float*)d_out;
    (void)in_sizes; (void)out_size;

    cudaFuncSetAttribute(att_kernel, cudaFuncAttributeMaxDynamicSharedMemorySize, S_TOTAL);

    rowstats_kernel<<<Nn, 256>>>(dist, locp);
    value_kernel<<<dim3(Nn / 64, Hh), 512>>>(inputs, weight);
    att_kernel<<<dim3(Nn / 128, Hh), 256, S_TOTAL>>>(dist, r, locp, out);
}